// round 1
// baseline (speedup 1.0000x reference)
#include <cuda_runtime.h>
#include <math.h>

#define HD 128
#define NN 256
#define BB 16

// Scratch (device globals: no allocation allowed)
__device__ float g_hA[NN * HD];
__device__ float g_hB[NN * HD];
__device__ float g_A0[NN * HD];
__device__ float g_Bm0[NN * HD];
__device__ float g_sigma[BB];

// ---------------------------------------------------------------------------
// K1: per-batch embedding; b==0: layer-0 closed form -> g_hA
//     b>=1: full 3-layer chain + edge-MLP scalar -> g_sigma[b]
// grid 16 x block 128
// ---------------------------------------------------------------------------
__global__ __launch_bounds__(128) void k_emb_chain(
    const float* __restrict__ z, const float* __restrict__ We,
    const float* __restrict__ be, const float* __restrict__ Wg,
    const float* __restrict__ bg, const float* __restrict__ W1a,
    const float* __restrict__ W1b, const float* __restrict__ b1,
    const float* __restrict__ W2, const float* __restrict__ b2)
{
    const int b = blockIdx.x;
    const int d = threadIdx.x;
    __shared__ float sz[64];
    __shared__ float sv[HD];
    __shared__ float red[HD];
    __shared__ float alpha[NN];

    if (d < 64) sz[d] = z[b * 64 + d];
    __syncthreads();

    float acc = be[d];
#pragma unroll 8
    for (int k = 0; k < 64; k++) acc = fmaf(sz[k], We[k * HD + d], acc);
    sv[d] = acc;
    __syncthreads();

    if (b == 0) {
        // w[d] = emb0 @ Wg[0]
        float w = 0.f;
#pragma unroll 8
        for (int k = 0; k < HD; k++) w = fmaf(sv[k], Wg[k * HD + d], w);
        const float bgv = bg[d];
        if (d == 0) {
            float c = 0.f;
            for (int n = 0; n < NN; n++) {
                float di = rsqrtf((float)(n + 1));
                alpha[n] = di * c + di * di;   // dinv*excl_prefix(dinv) + dinv^2
                c += di;
            }
        }
        __syncthreads();
        for (int n = 0; n < NN; n++)
            g_hA[n * HD + d] = fmaxf(fmaf(alpha[n], w, bgv), 0.f);
    } else {
        float v = acc;
#pragma unroll 1
        for (int l = 0; l < 3; l++) {
            __syncthreads();
            sv[d] = v;
            __syncthreads();
            float u = bg[l * HD + d];
            const float* Wl = Wg + l * HD * HD;
#pragma unroll 8
            for (int k = 0; k < HD; k++) u = fmaf(sv[k], Wl[k * HD + d], u);
            v = fmaxf(u, 0.f);
        }
        __syncthreads();
        sv[d] = v;
        __syncthreads();
        float a = b1[d], m = 0.f;
#pragma unroll 8
        for (int k = 0; k < HD; k++) {
            float vk = sv[k];
            a = fmaf(vk, W1a[k * HD + d], a);
            m = fmaf(vk, W1b[k * HD + d], m);
        }
        red[d] = fmaxf(a + m, 0.f) * W2[d];
        __syncthreads();
        for (int s = 64; s > 0; s >>= 1) {
            if (d < s) red[d] += red[d + s];
            __syncthreads();
        }
        if (d == 0) {
            float c = red[0] + b2[0];
            g_sigma[b] = 1.f / (1.f + expf(-c));
        }
    }
}

// ---------------------------------------------------------------------------
// K2: batch-0 GCN layer l (l = 1 or 2): GEMM (256x128 @ 128x128 column chunk)
//     + exclusive prefix aggregation over nodes + relu.
// grid 32 (4 dims each) x block 256 (one thread per node for GEMM)
// flag==0: g_hA -> g_hB ; flag==1: g_hB -> g_hA
// ---------------------------------------------------------------------------
__global__ __launch_bounds__(256) void k_gcn(
    const float* __restrict__ Wg, const float* __restrict__ bg,
    int l, int flag)
{
    const int DC = 4;
    const float* src = flag ? g_hB : g_hA;
    float* dst       = flag ? g_hA : g_hB;
    const int dbase = blockIdx.x * DC;
    __shared__ float sW[HD][DC];
    __shared__ float shw[NN][DC + 1];   // pad: conflict-free column scans
    const int tid = threadIdx.x;

    for (int i = tid; i < HD * DC; i += 256) {
        int k = i / DC, j = i % DC;
        sW[k][j] = Wg[l * HD * HD + k * HD + dbase + j];
    }
    __syncthreads();

    const int n = tid;
    float a0 = 0.f, a1 = 0.f, a2 = 0.f, a3 = 0.f;
    const float4* row = (const float4*)(src + n * HD);
#pragma unroll
    for (int k4 = 0; k4 < HD / 4; k4++) {
        float4 h4 = row[k4];
        int k = k4 * 4;
        a0 = fmaf(h4.x, sW[k][0], a0); a1 = fmaf(h4.x, sW[k][1], a1);
        a2 = fmaf(h4.x, sW[k][2], a2); a3 = fmaf(h4.x, sW[k][3], a3);
        a0 = fmaf(h4.y, sW[k+1][0], a0); a1 = fmaf(h4.y, sW[k+1][1], a1);
        a2 = fmaf(h4.y, sW[k+1][2], a2); a3 = fmaf(h4.y, sW[k+1][3], a3);
        a0 = fmaf(h4.z, sW[k+2][0], a0); a1 = fmaf(h4.z, sW[k+2][1], a1);
        a2 = fmaf(h4.z, sW[k+2][2], a2); a3 = fmaf(h4.z, sW[k+2][3], a3);
        a0 = fmaf(h4.w, sW[k+3][0], a0); a1 = fmaf(h4.w, sW[k+3][1], a1);
        a2 = fmaf(h4.w, sW[k+3][2], a2); a3 = fmaf(h4.w, sW[k+3][3], a3);
    }
    shw[n][0] = a0; shw[n][1] = a1; shw[n][2] = a2; shw[n][3] = a3;
    __syncthreads();

    const int warp = tid >> 5, lane = tid & 31;
    if (warp < DC) {
        const int j = warp;
        const float bgv = bg[l * HD + dbase + j];
        float carry = 0.f;
#pragma unroll
        for (int c = 0; c < NN / 32; c++) {
            int nn = c * 32 + lane;
            float hw = shw[nn][j];
            float di = rsqrtf((float)(nn + 1));
            float s = hw * di;
            float v = s;
#pragma unroll
            for (int off = 1; off < 32; off <<= 1) {
                float t = __shfl_up_sync(0xffffffffu, v, off);
                if (lane >= off) v += t;
            }
            float incl = v + carry;
            float excl = incl - s;
            float res = fmaxf(di * excl + hw * di * di + bgv, 0.f);
            dst[nn * HD + dbase + j] = res;
            carry = __shfl_sync(0xffffffffu, incl, 31);
        }
    }
}

// ---------------------------------------------------------------------------
// K3: batch-0 edge prep: A0 = h@W1a + b1, Bm0 = h@W1b  (h in g_hA)
// grid 32 (4 dims) x block 256
// ---------------------------------------------------------------------------
__global__ __launch_bounds__(256) void k_edgeprep(
    const float* __restrict__ W1a, const float* __restrict__ W1b,
    const float* __restrict__ b1)
{
    const int DC = 4;
    const int dbase = blockIdx.x * DC;
    __shared__ float sWa[HD][DC], sWb[HD][DC];
    const int tid = threadIdx.x;
    for (int i = tid; i < HD * DC; i += 256) {
        int k = i / DC, j = i % DC;
        sWa[k][j] = W1a[k * HD + dbase + j];
        sWb[k][j] = W1b[k * HD + dbase + j];
    }
    __syncthreads();

    const int n = tid;
    float aa[DC] = {0.f, 0.f, 0.f, 0.f};
    float mm[DC] = {0.f, 0.f, 0.f, 0.f};
    const float4* row = (const float4*)(g_hA + n * HD);
#pragma unroll
    for (int k4 = 0; k4 < HD / 4; k4++) {
        float4 h4 = row[k4];
        float hv[4] = {h4.x, h4.y, h4.z, h4.w};
#pragma unroll
        for (int e = 0; e < 4; e++) {
            int k = k4 * 4 + e;
#pragma unroll
            for (int j = 0; j < DC; j++) {
                aa[j] = fmaf(hv[e], sWa[k][j], aa[j]);
                mm[j] = fmaf(hv[e], sWb[k][j], mm[j]);
            }
        }
    }
#pragma unroll
    for (int j = 0; j < DC; j++) {
        g_A0[n * HD + dbase + j]  = aa[j] + b1[dbase + j];
        g_Bm0[n * HD + dbase + j] = mm[j];
    }
}

// ---------------------------------------------------------------------------
// K4: output fill.
//  y==0  : batch 0 — block i computes pairs (i,j), j>i: warp-per-pair
//          128-d relu-dot with W2, sigmoid, write (i,j) and (j,i); diag=0.
//  y>=1  : constant fill sigma[y] off-diagonal, 0 on diagonal.
// grid (256,16) x block 256
// ---------------------------------------------------------------------------
__global__ __launch_bounds__(256) void k_fill(
    float* __restrict__ out, const float* __restrict__ W2,
    const float* __restrict__ b2)
{
    const int b = blockIdx.y;
    const int tid = threadIdx.x;
    if (b == 0) {
        const int i = blockIdx.x;
        __shared__ float sA[HD], sW2[HD];
        if (tid < HD) { sA[tid] = g_A0[i * HD + tid]; sW2[tid] = W2[tid]; }
        __syncthreads();
        if (tid == 0) out[i * NN + i] = 0.f;
        const int warp = tid >> 5, lane = tid & 31;
        const float b2v = b2[0];
        const int d = lane * 4;
        for (int j = i + 1 + warp; j < NN; j += 8) {
            float4 v = ((const float4*)(g_Bm0 + j * HD))[lane];
            float r = fmaxf(sA[d]     + v.x, 0.f) * sW2[d]
                    + fmaxf(sA[d + 1] + v.y, 0.f) * sW2[d + 1]
                    + fmaxf(sA[d + 2] + v.z, 0.f) * sW2[d + 2]
                    + fmaxf(sA[d + 3] + v.w, 0.f) * sW2[d + 3];
#pragma unroll
            for (int off = 16; off > 0; off >>= 1)
                r += __shfl_xor_sync(0xffffffffu, r, off);
            if (lane == 0) {
                float p = 1.f / (1.f + expf(-(r + b2v)));
                out[i * NN + j] = p;
                out[j * NN + i] = p;
            }
        }
    } else {
        const float val = g_sigma[b];
        const int idx = blockIdx.x * 256 + tid;       // 0..65535
        const int i = idx >> 8, j = idx & 255;
        out[b * NN * NN + idx] = (i == j) ? 0.f : val;
    }
}

// ---------------------------------------------------------------------------
extern "C" void kernel_launch(void* const* d_in, const int* in_sizes, int n_in,
                              void* d_out, int out_size)
{
    const float* z   = (const float*)d_in[0];
    const float* We  = (const float*)d_in[1];
    const float* be  = (const float*)d_in[2];
    const float* Wg  = (const float*)d_in[3];
    const float* bg  = (const float*)d_in[4];
    const float* W1a = (const float*)d_in[5];
    const float* W1b = (const float*)d_in[6];
    const float* b1  = (const float*)d_in[7];
    const float* W2  = (const float*)d_in[8];
    const float* b2  = (const float*)d_in[9];
    float* out = (float*)d_out;

    k_emb_chain<<<16, 128>>>(z, We, be, Wg, bg, W1a, W1b, b1, W2, b2);
    k_gcn<<<32, 256>>>(Wg, bg, 1, 0);   // g_hA -> g_hB
    k_gcn<<<32, 256>>>(Wg, bg, 2, 1);   // g_hB -> g_hA
    k_edgeprep<<<32, 256>>>(W1a, W1b, b1);
    dim3 g4(256, 16);
    k_fill<<<g4, 256>>>(out, W2, b2);
}

// round 12
// speedup vs baseline: 1.6291x; 1.6291x over previous
#include <cuda_runtime.h>
#include <math.h>

#define HD 128
#define NN 256
#define BB 16
#define LATD 64
#define TILES 136   // 16x16 node tiles, ti<=tj: 16*17/2

// Scratch (device globals: no allocation allowed)
__device__ float g_hA[NN * HD];
__device__ float g_hB[NN * HD];
__device__ float g_A0[NN * HD];
__device__ float g_Bm0[NN * HD];
__device__ float g_sigma[BB];

// ---------------------------------------------------------------------------
// K1: per-batch. 512 threads = 4-way K split (q) x 128 dims (d).
//  b==0: emb -> w = emb@Wg0 -> closed-form layer-0 h  (g_hA)
//  b>=1: emb -> 3 dense+relu -> edge-MLP scalar -> g_sigma[b]
// ---------------------------------------------------------------------------
__global__ __launch_bounds__(512) void k_emb_chain(
    const float* __restrict__ z, const float* __restrict__ We,
    const float* __restrict__ be, const float* __restrict__ Wg,
    const float* __restrict__ bg, const float* __restrict__ W1a,
    const float* __restrict__ W1b, const float* __restrict__ b1,
    const float* __restrict__ W2, const float* __restrict__ b2)
{
    const int b = blockIdx.x;
    const int tid = threadIdx.x;
    const int q = tid >> 7;        // 0..3
    const int d = tid & 127;
    __shared__ float sz[LATD];
    __shared__ float red[4][HD];
    __shared__ float redm[4][HD];
    __shared__ float sva[HD], svb[HD];
    __shared__ float w_sh[HD];
    __shared__ float salpha[NN];
    __shared__ float csum8[8];
    __shared__ float wsum[4];

    if (tid < LATD) sz[tid] = z[b * LATD + tid];
    __syncthreads();

    // embedding: emb[d] = z_b . We[:,d] + be[d]
    float p = 0.f;
#pragma unroll
    for (int kk = 0; kk < 16; kk++) {
        int k = q * 16 + kk;
        p = fmaf(sz[k], We[k * HD + d], p);
    }
    red[q][d] = p;
    __syncthreads();
    if (q == 0) sva[d] = red[0][d] + red[1][d] + red[2][d] + red[3][d] + be[d];
    __syncthreads();

    if (b == 0) {
        // w[d] = emb0 @ Wg[0][:,d]
        p = 0.f;
#pragma unroll
        for (int kk = 0; kk < 32; kk++) {
            int k = q * 32 + kk;
            p = fmaf(sva[k], Wg[k * HD + d], p);
        }
        red[q][d] = p;
        // alpha[n] = dinv[n] * inclusive_prefix(dinv)[n]  (warp scans, warps 0-7)
        float di = 0.f, incl = 0.f; int c = 0;
        const int lane = tid & 31;
        if (tid < NN) {
            di = rsqrtf((float)(tid + 1));
            incl = di;
#pragma unroll
            for (int off = 1; off < 32; off <<= 1) {
                float t = __shfl_up_sync(0xffffffffu, incl, off);
                if (lane >= off) incl += t;
            }
            c = tid >> 5;
            if (lane == 31) csum8[c] = incl;
        }
        __syncthreads();
        if (q == 0) w_sh[d] = red[0][d] + red[1][d] + red[2][d] + red[3][d];
        if (tid < NN) {
            float off = 0.f;
#pragma unroll
            for (int cc = 0; cc < 7; cc++)
                if (cc < c) off += csum8[cc];
            salpha[tid] = di * (off + incl);
        }
        __syncthreads();
        // h1[n][d] = relu(alpha[n]*w[d] + bg0[d]); vectorized stores
        const float4* w4 = (const float4*)w_sh;
        const float4* bg4 = (const float4*)bg;
#pragma unroll
        for (int i = 0; i < 16; i++) {
            int e = i * 512 + tid;          // float4 index, 8192 total
            int n = e >> 5, d4 = e & 31;
            float4 wv = w4[d4];
            float4 bv = bg4[d4];
            float a = salpha[n];
            float4 r;
            r.x = fmaxf(fmaf(a, wv.x, bv.x), 0.f);
            r.y = fmaxf(fmaf(a, wv.y, bv.y), 0.f);
            r.z = fmaxf(fmaf(a, wv.z, bv.z), 0.f);
            r.w = fmaxf(fmaf(a, wv.w, bv.w), 0.f);
            ((float4*)g_hA)[e] = r;
        }
    } else {
        float* cur = sva;
        float* nxt = svb;
        for (int l = 0; l < 3; l++) {
            const float* Wl = Wg + l * HD * HD;
            p = 0.f;
#pragma unroll
            for (int kk = 0; kk < 32; kk++) {
                int k = q * 32 + kk;
                p = fmaf(cur[k], Wl[k * HD + d], p);
            }
            red[q][d] = p;
            __syncthreads();
            if (q == 0)
                nxt[d] = fmaxf(red[0][d] + red[1][d] + red[2][d] + red[3][d]
                               + bg[l * HD + d], 0.f);
            __syncthreads();
            float* t = cur; cur = nxt; nxt = t;
        }
        // edge MLP scalar
        float pa = 0.f, pm = 0.f;
#pragma unroll
        for (int kk = 0; kk < 32; kk++) {
            int k = q * 32 + kk;
            float v = cur[k];
            pa = fmaf(v, W1a[k * HD + d], pa);
            pm = fmaf(v, W1b[k * HD + d], pm);
        }
        red[q][d] = pa; redm[q][d] = pm;
        __syncthreads();
        if (q == 0) {
            float a = red[0][d] + red[1][d] + red[2][d] + red[3][d] + b1[d];
            float m = redm[0][d] + redm[1][d] + redm[2][d] + redm[3][d];
            float t = fmaxf(a + m, 0.f) * W2[d];
#pragma unroll
            for (int off = 16; off > 0; off >>= 1)
                t += __shfl_xor_sync(0xffffffffu, t, off);
            if ((tid & 31) == 0) wsum[d >> 5] = t;
        }
        __syncthreads();
        if (tid == 0) {
            float lg = wsum[0] + wsum[1] + wsum[2] + wsum[3] + b2[0];
            g_sigma[b] = __fdividef(1.f, 1.f + __expf(-lg));
        }
    }
}

// ---------------------------------------------------------------------------
// K2: batch-0 GCN layer l. 64 blocks x 2 dims each; 256 threads (1/node).
// GEMM with float2 weight LDS, then 8-warp two-level prefix scan:
//   res[n] = relu(dinv[n] * inclusive_prefix(hw*dinv)[n] + bg)
// flag==0: g_hA -> g_hB ; flag==1: g_hB -> g_hA
// ---------------------------------------------------------------------------
__global__ __launch_bounds__(256) void k_gcn(
    const float* __restrict__ Wg, const float* __restrict__ bg,
    int l, int flag)
{
    const float* src = flag ? g_hB : g_hA;
    float* dst       = flag ? g_hA : g_hB;
    const int dbase = blockIdx.x * 2;
    __shared__ float2 sw[HD];
    __shared__ float2 shw[NN];
    __shared__ float2 csum[8];
    const int tid = threadIdx.x;

    if (tid < HD) {
        const float* wp = Wg + l * HD * HD + tid * HD + dbase;
        sw[tid] = make_float2(wp[0], wp[1]);
    }
    __syncthreads();

    const int n = tid;
    float ax = 0.f, ay = 0.f;
    const float4* row = (const float4*)(src + n * HD);
#pragma unroll 8
    for (int k4 = 0; k4 < 32; k4++) {
        float4 h = row[k4];
        float2 w0 = sw[k4 * 4 + 0], w1 = sw[k4 * 4 + 1];
        float2 w2_ = sw[k4 * 4 + 2], w3 = sw[k4 * 4 + 3];
        ax = fmaf(h.x, w0.x, ax);  ay = fmaf(h.x, w0.y, ay);
        ax = fmaf(h.y, w1.x, ax);  ay = fmaf(h.y, w1.y, ay);
        ax = fmaf(h.z, w2_.x, ax); ay = fmaf(h.z, w2_.y, ay);
        ax = fmaf(h.w, w3.x, ax);  ay = fmaf(h.w, w3.y, ay);
    }
    shw[n] = make_float2(ax, ay);
    __syncthreads();

    // two-level scan: warp c scans nodes [c*32, c*32+32)
    const int c = tid >> 5, lane = tid & 31;
    float2 hw = shw[n];
    float di = rsqrtf((float)(n + 1));
    float ix = hw.x * di, iy = hw.y * di;
#pragma unroll
    for (int off = 1; off < 32; off <<= 1) {
        float tx = __shfl_up_sync(0xffffffffu, ix, off);
        float ty = __shfl_up_sync(0xffffffffu, iy, off);
        if (lane >= off) { ix += tx; iy += ty; }
    }
    if (lane == 31) csum[c] = make_float2(ix, iy);
    __syncthreads();
    float ox = 0.f, oy = 0.f;
#pragma unroll
    for (int cc = 0; cc < 7; cc++) {
        float2 t = csum[cc];
        if (cc < c) { ox += t.x; oy += t.y; }
    }
    float bgx = bg[l * HD + dbase], bgy = bg[l * HD + dbase + 1];
    float rx = fmaxf(fmaf(di, ox + ix, bgx), 0.f);
    float ry = fmaxf(fmaf(di, oy + iy, bgy), 0.f);
    *((float2*)(dst + n * HD + dbase)) = make_float2(rx, ry);
}

// ---------------------------------------------------------------------------
// K3: batch-0 edge prep: A0 = h@W1a + b1, Bm0 = h@W1b  (h in g_hA)
// grid (64 dim-pairs, 2 node halves) x 128 threads
// ---------------------------------------------------------------------------
__global__ __launch_bounds__(128) void k_edgeprep(
    const float* __restrict__ W1a, const float* __restrict__ W1b,
    const float* __restrict__ b1)
{
    const int dbase = blockIdx.x * 2;
    const int tid = threadIdx.x;
    const int n = blockIdx.y * 128 + tid;
    __shared__ float2 swa[HD], swb[HD];
    {
        const float* ap = W1a + tid * HD + dbase;
        const float* bp = W1b + tid * HD + dbase;
        swa[tid] = make_float2(ap[0], ap[1]);
        swb[tid] = make_float2(bp[0], bp[1]);
    }
    __syncthreads();

    float a0 = 0.f, a1 = 0.f, m0 = 0.f, m1 = 0.f;
    const float4* row = (const float4*)(g_hA + n * HD);
#pragma unroll 8
    for (int k4 = 0; k4 < 32; k4++) {
        float4 h = row[k4];
        float hv[4] = {h.x, h.y, h.z, h.w};
#pragma unroll
        for (int e = 0; e < 4; e++) {
            float2 wa = swa[k4 * 4 + e];
            float2 wb = swb[k4 * 4 + e];
            a0 = fmaf(hv[e], wa.x, a0); a1 = fmaf(hv[e], wa.y, a1);
            m0 = fmaf(hv[e], wb.x, m0); m1 = fmaf(hv[e], wb.y, m1);
        }
    }
    *((float2*)(g_A0 + n * HD + dbase)) =
        make_float2(a0 + b1[dbase], a1 + b1[dbase + 1]);
    *((float2*)(g_Bm0 + n * HD + dbase)) = make_float2(m0, m1);
}

// ---------------------------------------------------------------------------
// K4: output fill.
//  bid < 136: batch-0 16x16 pair tile (ti<=tj): shared-staged relu-dot,
//             write (i,j) and mirror (j,i); diag = 0.
//  else     : batches 1..15 constant fill via float4, diag zeroed.
// ---------------------------------------------------------------------------
__global__ __launch_bounds__(256) void k_fill(
    float* __restrict__ out, const float* __restrict__ W2,
    const float* __restrict__ b2)
{
    const int bid = blockIdx.x, tid = threadIdx.x;
    if (bid < TILES) {
        __shared__ float sA[16 * 132];
        __shared__ float sB[16 * 132];
        __shared__ float sW2[HD];
        __shared__ float sb2;
        int t = bid, ti = 0;
        while (t >= 16 - ti) { t -= 16 - ti; ti++; }
        int tj = ti + t;

        for (int i = tid; i < 512; i += 256) {
            int r = i >> 5, c4 = i & 31;
            float4 va = ((const float4*)(g_A0  + (ti * 16 + r) * HD))[c4];
            float4 vb = ((const float4*)(g_Bm0 + (tj * 16 + r) * HD))[c4];
            *((float4*)(sA + r * 132 + c4 * 4)) = va;
            *((float4*)(sB + r * 132 + c4 * 4)) = vb;
        }
        if (tid < HD) sW2[tid] = W2[tid];
        if (tid == 0) sb2 = b2[0];
        __syncthreads();

        const int i = tid >> 4, j = tid & 15;
        const float4* Ai = (const float4*)(sA + i * 132);
        const float4* Bj = (const float4*)(sB + j * 132);
        const float4* Wv = (const float4*)sW2;
        float acc = 0.f;
#pragma unroll 8
        for (int d4 = 0; d4 < 32; d4++) {
            float4 a = Ai[d4], bb = Bj[d4], w = Wv[d4];
            acc = fmaf(fmaxf(a.x + bb.x, 0.f), w.x, acc);
            acc = fmaf(fmaxf(a.y + bb.y, 0.f), w.y, acc);
            acc = fmaf(fmaxf(a.z + bb.z, 0.f), w.z, acc);
            acc = fmaf(fmaxf(a.w + bb.w, 0.f), w.w, acc);
        }
        const int gi = ti * 16 + i, gj = tj * 16 + j;
        if (gi < gj) {
            float pr = __fdividef(1.f, 1.f + __expf(-(acc + sb2)));
            out[gi * NN + gj] = pr;
            out[gj * NN + gi] = pr;
        } else if (gi == gj) {
            out[gi * NN + gi] = 0.f;
        }
    } else {
        const int r = bid - TILES;
        const int b = 1 + (r >> 4);
        const int chunk = r & 15;
        const float val = g_sigma[b];
        float4* ob = (float4*)(out + b * NN * NN);
#pragma unroll
        for (int u = 0; u < 4; u++) {
            int e4 = chunk * 1024 + u * 256 + tid;   // float4 idx in batch
            int e = e4 * 4;
            int dj = (e >> 8) - (e & 255);           // i - jbase
            float4 v = make_float4(val, val, val, val);
            if (dj == 0) v.x = 0.f;
            else if (dj == 1) v.y = 0.f;
            else if (dj == 2) v.z = 0.f;
            else if (dj == 3) v.w = 0.f;
            ob[e4] = v;
        }
    }
}

// ---------------------------------------------------------------------------
extern "C" void kernel_launch(void* const* d_in, const int* in_sizes, int n_in,
                              void* d_out, int out_size)
{
    const float* z   = (const float*)d_in[0];
    const float* We  = (const float*)d_in[1];
    const float* be  = (const float*)d_in[2];
    const float* Wg  = (const float*)d_in[3];
    const float* bg  = (const float*)d_in[4];
    const float* W1a = (const float*)d_in[5];
    const float* W1b = (const float*)d_in[6];
    const float* b1  = (const float*)d_in[7];
    const float* W2  = (const float*)d_in[8];
    const float* b2  = (const float*)d_in[9];
    float* out = (float*)d_out;

    k_emb_chain<<<16, 512>>>(z, We, be, Wg, bg, W1a, W1b, b1, W2, b2);
    k_gcn<<<64, 256>>>(Wg, bg, 1, 0);          // g_hA -> g_hB
    k_gcn<<<64, 256>>>(Wg, bg, 2, 1);          // g_hB -> g_hA
    k_edgeprep<<<dim3(64, 2), 128>>>(W1a, W1b, b1);
    k_fill<<<TILES + 15 * 16, 256>>>(out, W2, b2);
}